// round 12
// baseline (speedup 1.0000x reference)
#include <cuda_runtime.h>
#include <cuda_fp16.h>
#include <cstdint>

#define EMBED 64
#define HID   128
#define MAXN  1000000
#define TILE_M 128
#define NTH   256

// Scratch: messages[N, 64]. __device__ global (no allocation allowed).
__device__ float g_msgs[(size_t)MAXN * EMBED];

// ---------------------------------------------------------------------------
// smem layout (bytes). x/w1 rows: 72 u16 (144 B); hs/w2 rows: 136 u16 (272 B).
// Both give row-stride ≡ 16 (mod 128) B -> ldmatrix 8-row wavefronts hit all
// eight 16B bank groups -> conflict-free.
// ---------------------------------------------------------------------------
#define STRX 72
#define STRH 136
#define OFF_XHI  0
#define OFF_XLO  (OFF_XHI  + 128*STRX*2)
#define OFF_W1HI (OFF_XLO  + 128*STRX*2)
#define OFF_W2HI (OFF_W1HI + 128*STRX*2)
#define OFF_HSHI (OFF_W2HI + 64*STRH*2)
#define OFF_HSLO (OFF_HSHI + 128*STRH*2)
#define OFF_B1   (OFF_HSLO + 128*STRH*2)
#define OFF_B2   (OFF_B1 + 128*4)
#define SMEM_TOT (OFF_B2 + 64*4)          /* ~143 KB */

// ---------------------------------------------------------------------------
// PTX helpers
// ---------------------------------------------------------------------------
__device__ __forceinline__ uint32_t smem_u32(const void* p) {
    uint32_t a;
    asm("{ .reg .u64 t; cvta.to.shared.u64 t, %1; cvt.u32.u64 %0, t; }"
        : "=r"(a) : "l"(p));
    return a;
}
__device__ __forceinline__ void ldm4(uint32_t r[4], uint32_t addr) {
    asm volatile("ldmatrix.sync.aligned.m8n8.x4.shared.b16 {%0,%1,%2,%3}, [%4];"
                 : "=r"(r[0]), "=r"(r[1]), "=r"(r[2]), "=r"(r[3]) : "r"(addr));
}
__device__ __forceinline__ void mma16816(float c[4], const uint32_t a[4],
                                         uint32_t b0, uint32_t b1) {
    asm volatile(
        "mma.sync.aligned.m16n8k16.row.col.f32.f16.f16.f32 "
        "{%0,%1,%2,%3}, {%4,%5,%6,%7}, {%8,%9}, {%0,%1,%2,%3};"
        : "+f"(c[0]), "+f"(c[1]), "+f"(c[2]), "+f"(c[3])
        : "r"(a[0]), "r"(a[1]), "r"(a[2]), "r"(a[3]), "r"(b0), "r"(b1));
}
// split f32 -> fp16 hi + fp16 lo (lo = v - (float)hi)
__device__ __forceinline__ void split2(float v, __half& hi, __half& lo) {
    hi = __float2half_rn(v);
    lo = __float2half_rn(v - __half2float(hi));
}
__device__ __forceinline__ uint32_t packh2(__half a, __half b) {  // a -> low
    __half2 h = __halves2half2(a, b);
    return *reinterpret_cast<uint32_t*>(&h);
}

// ---------------------------------------------------------------------------
// Kernel 0: no-op probe (keeps ncu -s 5 -c 1 landing on the MLP kernel)
// ---------------------------------------------------------------------------
__global__ void probe_kernel(int x) { (void)x; }

// ---------------------------------------------------------------------------
// Kernel 1: zero the message buffer
// ---------------------------------------------------------------------------
__global__ void zero_msgs_kernel(int n4) {
    int i = blockIdx.x * blockDim.x + threadIdx.x;
    if (i < n4) reinterpret_cast<float4*>(g_msgs)[i] = make_float4(0.f, 0.f, 0.f, 0.f);
}

// ---------------------------------------------------------------------------
// Kernel 2: scatter-add  messages[dst] += emb[src]   (edge_index int32)
// ---------------------------------------------------------------------------
__global__ void scatter_kernel(const int* __restrict__ ei,
                               const float* __restrict__ emb, int E) {
    long long idx = (long long)blockIdx.x * blockDim.x + threadIdx.x;
    if (idx >= (long long)E * 16) return;
    int e  = (int)(idx >> 4);
    int d4 = (int)(idx & 15);
    int src = ei[e];
    int dst = ei[E + e];
    float4 v = reinterpret_cast<const float4*>(emb + (size_t)src * EMBED)[d4];
    float* o = g_msgs + (size_t)dst * EMBED + d4 * 4;
    asm volatile("red.global.add.v4.f32 [%0], {%1, %2, %3, %4};"
                 :: "l"(o), "f"(v.x), "f"(v.y), "f"(v.z), "f"(v.w)
                 : "memory");
}

// ---------------------------------------------------------------------------
// Kernel 3: fused 2-layer MLP + residual on mma.sync fp16, 2-product split:
//   a*b ~= a_hi*b_hi + a_lo*b_hi   (dropped a_hi*b_lo ~ 2^-12 rel)
// Persistent, 256 threads = 8 warps; warp w owns node rows [16w, 16w+16).
// B (weights) staged hi-only -> 33% fewer MMAs, 27% fewer LDSMs than R9.
// ---------------------------------------------------------------------------
__global__ void __launch_bounds__(NTH) mlp_mma_kernel(
    const float* __restrict__ emb,
    const float* __restrict__ w1, const float* __restrict__ b1,
    const float* __restrict__ w2, const float* __restrict__ b2,
    float* __restrict__ out, int N, int ntiles)
{
    extern __shared__ char smem[];
    const uint32_t sb = smem_u32(smem);
    float* b1s = (float*)(smem + OFF_B1);
    float* b2s = (float*)(smem + OFF_B2);

    const int tid  = threadIdx.x;
    const int lane = tid & 31;
    const int wrp  = tid >> 5;          // 0..7
    const int mrow = wrp * 16;

    // ---- stage weights (fp16 hi only) ONCE ----
    for (int i = tid; i < HID * EMBED; i += NTH) {      // w1[h][d]
        int h = i >> 6, d = i & 63;
        *(__half*)(smem + OFF_W1HI + (h * STRX + d) * 2) = __float2half_rn(w1[i]);
    }
    for (int i = tid; i < EMBED * HID; i += NTH) {      // w2[n][k]
        int n = i >> 7, k = i & 127;
        *(__half*)(smem + OFF_W2HI + (n * STRH + k) * 2) = __float2half_rn(w2[i]);
    }
    if (tid < HID)   b1s[tid] = b1[tid];
    if (tid < EMBED) b2s[tid] = b2[tid];

    const int dcol = 2 * (lane & 3);    // D-frag col within 8-wide tile
    const int drow = lane >> 2;         // D-frag row within 16-tall tile

    for (int tile = blockIdx.x; tile < ntiles; tile += gridDim.x) {
        const int node0 = tile * TILE_M;

        // ---- stage x tile: f32 -> fp16 hi/lo ----
        #pragma unroll
        for (int j = 0; j < 8; j++) {
            int lin = tid + j * NTH;      // 2048 float4 units
            int c4 = lin & 15, m = lin >> 4;
            int node = node0 + m;
            float4 v = make_float4(0.f, 0.f, 0.f, 0.f);
            if (node < N)
                v = reinterpret_cast<const float4*>(g_msgs + (size_t)node * EMBED)[c4];
            __half h0, h1, h2, h3, l0, l1, l2, l3;
            split2(v.x, h0, l0); split2(v.y, h1, l1);
            split2(v.z, h2, l2); split2(v.w, h3, l3);
            uint32_t off = (uint32_t)(m * STRX + c4 * 4) * 2;  // bytes
            *(uint2*)(smem + OFF_XHI + off) = make_uint2(packh2(h0, h1), packh2(h2, h3));
            *(uint2*)(smem + OFF_XLO + off) = make_uint2(packh2(l0, l1), packh2(l2, l3));
        }
        __syncthreads();

        // ---------------- GEMM1: 16 m x 128 h per warp ----------------
        float acc[16][4];
        #pragma unroll
        for (int nt = 0; nt < 16; nt++) {
            float bb0 = b1s[nt * 8 + dcol], bb1 = b1s[nt * 8 + dcol + 1];
            acc[nt][0] = bb0; acc[nt][1] = bb1; acc[nt][2] = bb0; acc[nt][3] = bb1;
        }
        {
            const uint32_t a_off = (uint32_t)((mrow + (lane & 15)) * STRX) * 2
                                   + (uint32_t)(lane >> 4) * 16;
            #pragma unroll
            for (int ks = 0; ks < 4; ks++) {
                uint32_t ahi[4], alo[4];
                ldm4(ahi, sb + OFF_XHI + a_off + ks * 32);
                ldm4(alo, sb + OFF_XLO + a_off + ks * 32);
                const uint32_t b_lane = (uint32_t)(lane & 15) * (STRX * 2)
                                        + (uint32_t)(lane >> 4) * 16 + ks * 32;
                #pragma unroll
                for (int pr = 0; pr < 8; pr++) {
                    uint32_t bh[4];
                    uint32_t boff = (uint32_t)(pr * 16) * (STRX * 2) + b_lane;
                    ldm4(bh, sb + OFF_W1HI + boff);
                    mma16816(acc[2*pr],   ahi, bh[0], bh[2]);
                    mma16816(acc[2*pr],   alo, bh[0], bh[2]);
                    mma16816(acc[2*pr+1], ahi, bh[1], bh[3]);
                    mma16816(acc[2*pr+1], alo, bh[1], bh[3]);
                }
            }
        }
        // ---- epi1: relu, split -> hs hi/lo ----
        #pragma unroll
        for (int nt = 0; nt < 16; nt++) {
            float f0 = fmaxf(acc[nt][0], 0.f), f1 = fmaxf(acc[nt][1], 0.f);
            float f2 = fmaxf(acc[nt][2], 0.f), f3 = fmaxf(acc[nt][3], 0.f);
            __half h0, h1, h2, h3, l0, l1, l2, l3;
            split2(f0, h0, l0); split2(f1, h1, l1);
            split2(f2, h2, l2); split2(f3, h3, l3);
            int col = nt * 8 + dcol;
            uint32_t o0 = (uint32_t)((mrow + drow) * STRH + col) * 2;
            uint32_t o1 = (uint32_t)((mrow + drow + 8) * STRH + col) * 2;
            *(uint32_t*)(smem + OFF_HSHI + o0) = packh2(h0, h1);
            *(uint32_t*)(smem + OFF_HSLO + o0) = packh2(l0, l1);
            *(uint32_t*)(smem + OFF_HSHI + o1) = packh2(h2, h3);
            *(uint32_t*)(smem + OFF_HSLO + o1) = packh2(l2, l3);
        }
        __syncthreads();

        // ---------------- GEMM2: 16 m x 64 n per warp ----------------
        float acc2[8][4];
        #pragma unroll
        for (int nt = 0; nt < 8; nt++) {
            float bb0 = b2s[nt * 8 + dcol], bb1 = b2s[nt * 8 + dcol + 1];
            acc2[nt][0] = bb0; acc2[nt][1] = bb1; acc2[nt][2] = bb0; acc2[nt][3] = bb1;
        }
        {
            const uint32_t a_off = (uint32_t)((mrow + (lane & 15)) * STRH) * 2
                                   + (uint32_t)(lane >> 4) * 16;
            #pragma unroll
            for (int ks = 0; ks < 8; ks++) {
                uint32_t ahi[4], alo[4];
                ldm4(ahi, sb + OFF_HSHI + a_off + ks * 32);
                ldm4(alo, sb + OFF_HSLO + a_off + ks * 32);
                const uint32_t b_lane = (uint32_t)(lane & 15) * (STRH * 2)
                                        + (uint32_t)(lane >> 4) * 16 + ks * 32;
                #pragma unroll
                for (int pr = 0; pr < 4; pr++) {
                    uint32_t bh[4];
                    uint32_t boff = (uint32_t)(pr * 16) * (STRH * 2) + b_lane;
                    ldm4(bh, sb + OFF_W2HI + boff);
                    mma16816(acc2[2*pr],   ahi, bh[0], bh[2]);
                    mma16816(acc2[2*pr],   alo, bh[0], bh[2]);
                    mma16816(acc2[2*pr+1], ahi, bh[1], bh[3]);
                    mma16816(acc2[2*pr+1], alo, bh[1], bh[3]);
                }
            }
        }
        // ---- epi2: relu + residual, float2 stores ----
        {
            int r0 = node0 + mrow + drow;
            int r1 = r0 + 8;
            #pragma unroll
            for (int nt = 0; nt < 8; nt++) {
                int n = nt * 8 + dcol;
                if (r0 < N) {
                    float2 e = *(const float2*)(emb + (size_t)r0 * EMBED + n);
                    float2 o;
                    o.x = e.x + fmaxf(acc2[nt][0], 0.f);
                    o.y = e.y + fmaxf(acc2[nt][1], 0.f);
                    *(float2*)(out + (size_t)r0 * EMBED + n) = o;
                }
                if (r1 < N) {
                    float2 e = *(const float2*)(emb + (size_t)r1 * EMBED + n);
                    float2 o;
                    o.x = e.x + fmaxf(acc2[nt][2], 0.f);
                    o.y = e.y + fmaxf(acc2[nt][3], 0.f);
                    *(float2*)(out + (size_t)r1 * EMBED + n) = o;
                }
            }
        }
        __syncthreads();   // xs/hs safe to overwrite next tile
    }
}

// ---------------------------------------------------------------------------
// Launch
// ---------------------------------------------------------------------------
extern "C" void kernel_launch(void* const* d_in, const int* in_sizes, int n_in,
                              void* d_out, int out_size) {
    const int*   ei  = (const int*)d_in[0];   // edge_index [2, E] int32
    const float* emb = (const float*)d_in[1]; // [N, 64]
    const float* w1  = (const float*)d_in[2]; // [128, 64]
    const float* b1  = (const float*)d_in[3]; // [128]
    const float* w2  = (const float*)d_in[4]; // [64, 128]
    const float* b2  = (const float*)d_in[5]; // [64]
    float*       out = (float*)d_out;

    int E = in_sizes[0] / 2;
    int N = in_sizes[1] / EMBED;

    static int nsm = 0;
    if (nsm == 0) {
        cudaDeviceGetAttribute(&nsm, cudaDevAttrMultiProcessorCount, 0);
        if (nsm <= 0) nsm = 148;
    }

    // 0) capture-alignment probe (no-op)
    probe_kernel<<<1, 32>>>(0);

    // 1) zero messages
    int n4 = N * (EMBED / 4);
    zero_msgs_kernel<<<(n4 + 255) / 256, 256>>>(n4);

    // 2) scatter-add
    long long total = (long long)E * 16;
    scatter_kernel<<<(unsigned)((total + 255) / 256), 256>>>(ei, emb, E);

    // 3) tensor-core (mma.sync fp16 2-product) fused MLP + residual
    cudaFuncSetAttribute(mlp_mma_kernel, cudaFuncAttributeMaxDynamicSharedMemorySize,
                         SMEM_TOT);
    int ntiles = (N + TILE_M - 1) / TILE_M;
    mlp_mma_kernel<<<nsm, NTH, SMEM_TOT>>>(emb, w1, b1, w2, b2, out, N, ntiles);
}

// round 13
// speedup vs baseline: 1.2460x; 1.2460x over previous
#include <cuda_runtime.h>
#include <cuda_bf16.h>
#include <cstdint>

#define EMBED 64
#define HID   128
#define MAXN  1000000
#define TILE_M 128
#define NTH   256

// Scratch: messages[N, 64]. __device__ global (no allocation allowed).
__device__ float g_msgs[(size_t)MAXN * EMBED];

// ---------------------------------------------------------------------------
// smem layout (bytes). x/w1 rows: 72 u16 (144 B); w2 rows: 136 u16 (272 B).
// Row strides ≡ 16 (mod 128) B -> ldmatrix wavefronts conflict-free.
// Hidden layer lives in REGISTERS (D->A fragment identity) -- no hs arrays.
// ---------------------------------------------------------------------------
#define STRX 72
#define STRH 136
#define OFF_XHI  0
#define OFF_XLO  (OFF_XHI  + 128*STRX*2)   /* 18432 */
#define OFF_W1HI (OFF_XLO  + 128*STRX*2)
#define OFF_W1LO (OFF_W1HI + 128*STRX*2)
#define OFF_W2HI (OFF_W1LO + 128*STRX*2)
#define OFF_W2LO (OFF_W2HI + 64*STRH*2)
#define OFF_B1   (OFF_W2LO + 64*STRH*2)
#define OFF_B2   (OFF_B1 + 128*4)
#define SMEM_TOT (OFF_B2 + 64*4)           /* 109,312 B -> 2 CTAs/SM */

// ---------------------------------------------------------------------------
// PTX helpers
// ---------------------------------------------------------------------------
__device__ __forceinline__ uint32_t smem_u32(const void* p) {
    uint32_t a;
    asm("{ .reg .u64 t; cvta.to.shared.u64 t, %1; cvt.u32.u64 %0, t; }"
        : "=r"(a) : "l"(p));
    return a;
}
__device__ __forceinline__ void ldm4(uint32_t r[4], uint32_t addr) {
    asm volatile("ldmatrix.sync.aligned.m8n8.x4.shared.b16 {%0,%1,%2,%3}, [%4];"
                 : "=r"(r[0]), "=r"(r[1]), "=r"(r[2]), "=r"(r[3]) : "r"(addr));
}
__device__ __forceinline__ void mma16816(float c[4], const uint32_t a[4],
                                         uint32_t b0, uint32_t b1) {
    asm volatile(
        "mma.sync.aligned.m16n8k16.row.col.f32.bf16.bf16.f32 "
        "{%0,%1,%2,%3}, {%4,%5,%6,%7}, {%8,%9}, {%0,%1,%2,%3};"
        : "+f"(c[0]), "+f"(c[1]), "+f"(c[2]), "+f"(c[3])
        : "r"(a[0]), "r"(a[1]), "r"(a[2]), "r"(a[3]), "r"(b0), "r"(b1));
}
// pack two f32 -> bf16x2 (hi_src -> bits[31:16], lo_src -> bits[15:0])
__device__ __forceinline__ uint32_t cvt2bf(float hi_src, float lo_src) {
    uint32_t r;
    asm("cvt.rn.bf16x2.f32 %0, %1, %2;" : "=r"(r) : "f"(hi_src), "f"(lo_src));
    return r;
}

// ---------------------------------------------------------------------------
// Kernel 0: no-op probe (keeps ncu -s 5 -c 1 landing on the MLP kernel)
// ---------------------------------------------------------------------------
__global__ void probe_kernel(int x) { (void)x; }

// ---------------------------------------------------------------------------
// Kernel 1: zero the message buffer
// ---------------------------------------------------------------------------
__global__ void zero_msgs_kernel(int n4) {
    int i = blockIdx.x * blockDim.x + threadIdx.x;
    if (i < n4) reinterpret_cast<float4*>(g_msgs)[i] = make_float4(0.f, 0.f, 0.f, 0.f);
}

// ---------------------------------------------------------------------------
// Kernel 2: scatter-add  messages[dst] += emb[src]   (edge_index int32)
// ---------------------------------------------------------------------------
__global__ void scatter_kernel(const int* __restrict__ ei,
                               const float* __restrict__ emb, int E) {
    long long idx = (long long)blockIdx.x * blockDim.x + threadIdx.x;
    if (idx >= (long long)E * 16) return;
    int e  = (int)(idx >> 4);
    int d4 = (int)(idx & 15);
    int src = ei[e];
    int dst = ei[E + e];
    float4 v = reinterpret_cast<const float4*>(emb + (size_t)src * EMBED)[d4];
    float* o = g_msgs + (size_t)dst * EMBED + d4 * 4;
    asm volatile("red.global.add.v4.f32 [%0], {%1, %2, %3, %4};"
                 :: "l"(o), "f"(v.x), "f"(v.y), "f"(v.z), "f"(v.w)
                 : "memory");
}

// ---------------------------------------------------------------------------
// Kernel 3: fused 2-layer MLP + residual, mma.sync bf16 3-product split.
// Persistent, 256 threads = 8 warps, 2 CTAs/SM (107 KB smem, <=128 regs).
// Hidden layer NEVER touches smem: GEMM1 D-fragments (two adjacent 8-wide
// n-tiles) are bit-identical in layout to GEMM2 A-fragments (16-wide k-chunk),
// so relu + bf16 hi/lo re-split happens in registers.
// ---------------------------------------------------------------------------
__global__ void __launch_bounds__(NTH, 2) mlp_mma_kernel(
    const float* __restrict__ emb,
    const float* __restrict__ w1, const float* __restrict__ b1,
    const float* __restrict__ w2, const float* __restrict__ b2,
    float* __restrict__ out, int N, int ntiles)
{
    extern __shared__ char smem[];
    const uint32_t sb = smem_u32(smem);
    float* b1s = (float*)(smem + OFF_B1);
    float* b2s = (float*)(smem + OFF_B2);

    const int tid  = threadIdx.x;
    const int lane = tid & 31;
    const int wrp  = tid >> 5;          // 0..7
    const int mrow = wrp * 16;

    // ---- stage weights hi/lo ONCE ----
    for (int i = tid; i < HID * EMBED; i += NTH) {      // w1[h][d]
        float v = w1[i];
        int h = i >> 6, d = i & 63;
        __nv_bfloat16 hb = __float2bfloat16(v);
        __nv_bfloat16 lb = __float2bfloat16(v - __bfloat162float(hb));
        *(uint16_t*)(smem + OFF_W1HI + (h * STRX + d) * 2) = __bfloat16_as_ushort(hb);
        *(uint16_t*)(smem + OFF_W1LO + (h * STRX + d) * 2) = __bfloat16_as_ushort(lb);
    }
    for (int i = tid; i < EMBED * HID; i += NTH) {      // w2[n][k]
        float v = w2[i];
        int n = i >> 7, k = i & 127;
        __nv_bfloat16 hb = __float2bfloat16(v);
        __nv_bfloat16 lb = __float2bfloat16(v - __bfloat162float(hb));
        *(uint16_t*)(smem + OFF_W2HI + (n * STRH + k) * 2) = __bfloat16_as_ushort(hb);
        *(uint16_t*)(smem + OFF_W2LO + (n * STRH + k) * 2) = __bfloat16_as_ushort(lb);
    }
    if (tid < HID)   b1s[tid] = b1[tid];
    if (tid < EMBED) b2s[tid] = b2[tid];

    const int dcol = 2 * (lane & 3);    // D-frag col within 8-wide tile
    const int drow = lane >> 2;         // D-frag row within 16-tall tile

    for (int tile = blockIdx.x; tile < ntiles; tile += gridDim.x) {
        const int node0 = tile * TILE_M;

        // ---- stage x tile: f32 -> bf16 hi/lo ----
        #pragma unroll
        for (int j = 0; j < 8; j++) {
            int lin = tid + j * NTH;      // 2048 float4 units
            int c4 = lin & 15, m = lin >> 4;
            int node = node0 + m;
            float4 v = make_float4(0.f, 0.f, 0.f, 0.f);
            if (node < N)
                v = reinterpret_cast<const float4*>(g_msgs + (size_t)node * EMBED)[c4];
            uint32_t p01 = cvt2bf(v.y, v.x);
            uint32_t p23 = cvt2bf(v.w, v.z);
            float h0 = __uint_as_float(p01 << 16);
            float h1 = __uint_as_float(p01 & 0xffff0000u);
            float h2 = __uint_as_float(p23 << 16);
            float h3 = __uint_as_float(p23 & 0xffff0000u);
            uint32_t l01 = cvt2bf(v.y - h1, v.x - h0);
            uint32_t l23 = cvt2bf(v.w - h3, v.z - h2);
            uint32_t off = (uint32_t)(m * STRX + c4 * 4) * 2;  // bytes
            *(uint2*)(smem + OFF_XHI + off) = make_uint2(p01, p23);
            *(uint2*)(smem + OFF_XLO + off) = make_uint2(l01, l23);
        }
        __syncthreads();

        // ---------------- GEMM1: 16 m x 128 h per warp ----------------
        float acc[16][4];
        #pragma unroll
        for (int nt = 0; nt < 16; nt++) {
            float bb0 = b1s[nt * 8 + dcol], bb1 = b1s[nt * 8 + dcol + 1];
            acc[nt][0] = bb0; acc[nt][1] = bb1; acc[nt][2] = bb0; acc[nt][3] = bb1;
        }
        {
            const uint32_t a_off = (uint32_t)((mrow + (lane & 15)) * STRX) * 2
                                   + (uint32_t)(lane >> 4) * 16;
            #pragma unroll
            for (int ks = 0; ks < 4; ks++) {
                uint32_t ahi[4], alo[4];
                ldm4(ahi, sb + OFF_XHI + a_off + ks * 32);
                ldm4(alo, sb + OFF_XLO + a_off + ks * 32);
                const uint32_t b_lane = (uint32_t)(lane & 15) * (STRX * 2)
                                        + (uint32_t)(lane >> 4) * 16 + ks * 32;
                #pragma unroll
                for (int pr = 0; pr < 8; pr++) {
                    uint32_t bh[4], bl[4];
                    uint32_t boff = (uint32_t)(pr * 16) * (STRX * 2) + b_lane;
                    ldm4(bh, sb + OFF_W1HI + boff);
                    ldm4(bl, sb + OFF_W1LO + boff);
                    mma16816(acc[2*pr],   ahi, bh[0], bh[2]);
                    mma16816(acc[2*pr],   ahi, bl[0], bl[2]);
                    mma16816(acc[2*pr],   alo, bh[0], bh[2]);
                    mma16816(acc[2*pr+1], ahi, bh[1], bh[3]);
                    mma16816(acc[2*pr+1], ahi, bl[1], bl[3]);
                    mma16816(acc[2*pr+1], alo, bh[1], bh[3]);
                }
            }
        }

        // ---- hidden in registers: relu + bf16 hi/lo split -> A-fragments.
        // k-chunk ks covers h-tiles {2ks, 2ks+1}:
        //   a0 = pack(c1,c0)[even], a1 = pack(c3,c2)[even],
        //   a2 = pack(c1,c0)[odd],  a3 = pack(c3,c2)[odd]
        uint32_t ah[8][4], al[8][4];
        #pragma unroll
        for (int ks = 0; ks < 8; ks++) {
            #pragma unroll
            for (int t = 0; t < 2; t++) {
                const float* a = acc[2 * ks + t];
                float f0 = fmaxf(a[0], 0.f), f1 = fmaxf(a[1], 0.f);
                float f2 = fmaxf(a[2], 0.f), f3 = fmaxf(a[3], 0.f);
                uint32_t ph01 = cvt2bf(f1, f0);
                uint32_t ph23 = cvt2bf(f3, f2);
                float h0 = __uint_as_float(ph01 << 16);
                float h1 = __uint_as_float(ph01 & 0xffff0000u);
                float h2 = __uint_as_float(ph23 << 16);
                float h3 = __uint_as_float(ph23 & 0xffff0000u);
                ah[ks][2 * t]     = ph01;
                ah[ks][2 * t + 1] = ph23;
                al[ks][2 * t]     = cvt2bf(f1 - h1, f0 - h0);
                al[ks][2 * t + 1] = cvt2bf(f3 - h3, f2 - h2);
            }
        }

        // ---------------- GEMM2: 16 m x 64 n per warp (A from regs) --------
        float acc2[8][4];
        #pragma unroll
        for (int nt = 0; nt < 8; nt++) {
            float bb0 = b2s[nt * 8 + dcol], bb1 = b2s[nt * 8 + dcol + 1];
            acc2[nt][0] = bb0; acc2[nt][1] = bb1; acc2[nt][2] = bb0; acc2[nt][3] = bb1;
        }
        {
            const uint32_t b_lane = (uint32_t)(lane & 15) * (STRH * 2)
                                    + (uint32_t)(lane >> 4) * 16;
            #pragma unroll
            for (int ks = 0; ks < 8; ks++) {
                #pragma unroll
                for (int pr = 0; pr < 4; pr++) {
                    uint32_t bh[4], bl[4];
                    uint32_t boff = (uint32_t)(pr * 16) * (STRH * 2) + b_lane
                                    + (uint32_t)ks * 32;
                    ldm4(bh, sb + OFF_W2HI + boff);
                    ldm4(bl, sb + OFF_W2LO + boff);
                    mma16816(acc2[2*pr],   ah[ks], bh[0], bh[2]);
                    mma16816(acc2[2*pr],   ah[ks], bl[0], bl[2]);
                    mma16816(acc2[2*pr],   al[ks], bh[0], bh[2]);
                    mma16816(acc2[2*pr+1], ah[ks], bh[1], bh[3]);
                    mma16816(acc2[2*pr+1], ah[ks], bl[1], bl[3]);
                    mma16816(acc2[2*pr+1], al[ks], bh[1], bh[3]);
                }
            }
        }
        // ---- epi2: relu + residual, float2 stores ----
        {
            int r0 = node0 + mrow + drow;
            int r1 = r0 + 8;
            #pragma unroll
            for (int nt = 0; nt < 8; nt++) {
                int n = nt * 8 + dcol;
                if (r0 < N) {
                    float2 e = *(const float2*)(emb + (size_t)r0 * EMBED + n);
                    float2 o;
                    o.x = e.x + fmaxf(acc2[nt][0], 0.f);
                    o.y = e.y + fmaxf(acc2[nt][1], 0.f);
                    *(float2*)(out + (size_t)r0 * EMBED + n) = o;
                }
                if (r1 < N) {
                    float2 e = *(const float2*)(emb + (size_t)r1 * EMBED + n);
                    float2 o;
                    o.x = e.x + fmaxf(acc2[nt][2], 0.f);
                    o.y = e.y + fmaxf(acc2[nt][3], 0.f);
                    *(float2*)(out + (size_t)r1 * EMBED + n) = o;
                }
            }
        }
        __syncthreads();   // xs safe to overwrite next tile
    }
}

// ---------------------------------------------------------------------------
// Launch
// ---------------------------------------------------------------------------
extern "C" void kernel_launch(void* const* d_in, const int* in_sizes, int n_in,
                              void* d_out, int out_size) {
    const int*   ei  = (const int*)d_in[0];   // edge_index [2, E] int32
    const float* emb = (const float*)d_in[1]; // [N, 64]
    const float* w1  = (const float*)d_in[2]; // [128, 64]
    const float* b1  = (const float*)d_in[3]; // [128]
    const float* w2  = (const float*)d_in[4]; // [64, 128]
    const float* b2  = (const float*)d_in[5]; // [64]
    float*       out = (float*)d_out;

    int E = in_sizes[0] / 2;
    int N = in_sizes[1] / EMBED;

    static int nsm = 0;
    if (nsm == 0) {
        cudaDeviceGetAttribute(&nsm, cudaDevAttrMultiProcessorCount, 0);
        if (nsm <= 0) nsm = 148;
    }

    // 0) capture-alignment probe (no-op)
    probe_kernel<<<1, 32>>>(0);

    // 1) zero messages
    int n4 = N * (EMBED / 4);
    zero_msgs_kernel<<<(n4 + 255) / 256, 256>>>(n4);

    // 2) scatter-add
    long long total = (long long)E * 16;
    scatter_kernel<<<(unsigned)((total + 255) / 256), 256>>>(ei, emb, E);

    // 3) tensor-core fused MLP + residual (bf16 3-product, 2 CTAs/SM,
    //    hidden in registers)
    cudaFuncSetAttribute(mlp_mma_kernel, cudaFuncAttributeMaxDynamicSharedMemorySize,
                         SMEM_TOT);
    int ntiles = (N + TILE_M - 1) / TILE_M;
    mlp_mma_kernel<<<nsm * 2, NTH, SMEM_TOT>>>(emb, w1, b1, w2, b2, out, N, ntiles);
}

// round 14
// speedup vs baseline: 1.4400x; 1.1557x over previous
#include <cuda_runtime.h>
#include <cuda_bf16.h>
#include <cstdint>

#define EMBED 64
#define HID   128
#define MAXN  1000000
#define NTH   256

// Scratch: messages[N, 64]. __device__ global (no allocation allowed).
__device__ float g_msgs[(size_t)MAXN * EMBED];

// ---------------------------------------------------------------------------
// smem layout (bytes): WEIGHTS ONLY (x never touches smem anymore).
// w1 rows: 72 u16 (144 B); w2 rows: 136 u16 (272 B) -> ldmatrix conflict-free.
// ---------------------------------------------------------------------------
#define STRX 72
#define STRH 136
#define OFF_W1HI 0
#define OFF_W1LO (OFF_W1HI + 128*STRX*2)
#define OFF_W2HI (OFF_W1LO + 128*STRX*2)
#define OFF_W2LO (OFF_W2HI + 64*STRH*2)
#define OFF_B1   (OFF_W2LO + 64*STRH*2)
#define OFF_B2   (OFF_B1 + 128*4)
#define SMEM_TOT (OFF_B2 + 64*4)           /* 72,448 B -> 2 CTAs/SM easily */

// ---------------------------------------------------------------------------
// PTX helpers
// ---------------------------------------------------------------------------
__device__ __forceinline__ uint32_t smem_u32(const void* p) {
    uint32_t a;
    asm("{ .reg .u64 t; cvta.to.shared.u64 t, %1; cvt.u32.u64 %0, t; }"
        : "=r"(a) : "l"(p));
    return a;
}
__device__ __forceinline__ void ldm4(uint32_t r[4], uint32_t addr) {
    asm volatile("ldmatrix.sync.aligned.m8n8.x4.shared.b16 {%0,%1,%2,%3}, [%4];"
                 : "=r"(r[0]), "=r"(r[1]), "=r"(r[2]), "=r"(r[3]) : "r"(addr));
}
__device__ __forceinline__ void mma16816(float c[4], const uint32_t a[4],
                                         uint32_t b0, uint32_t b1) {
    asm volatile(
        "mma.sync.aligned.m16n8k16.row.col.f32.bf16.bf16.f32 "
        "{%0,%1,%2,%3}, {%4,%5,%6,%7}, {%8,%9}, {%0,%1,%2,%3};"
        : "+f"(c[0]), "+f"(c[1]), "+f"(c[2]), "+f"(c[3])
        : "r"(a[0]), "r"(a[1]), "r"(a[2]), "r"(a[3]), "r"(b0), "r"(b1));
}
// pack two f32 -> bf16x2 (hi_src -> bits[31:16], lo_src -> bits[15:0])
__device__ __forceinline__ uint32_t cvt2bf(float hi_src, float lo_src) {
    uint32_t r;
    asm("cvt.rn.bf16x2.f32 %0, %1, %2;" : "=r"(r) : "f"(hi_src), "f"(lo_src));
    return r;
}
// split a float2 (v.x = lower col, v.y = upper col) into hi-frag + lo-frag regs
__device__ __forceinline__ void split_frag(float2 v, uint32_t& hi, uint32_t& lo) {
    uint32_t ph = cvt2bf(v.y, v.x);
    float hx = __uint_as_float(ph << 16);
    float hy = __uint_as_float(ph & 0xffff0000u);
    hi = ph;
    lo = cvt2bf(v.y - hy, v.x - hx);
}

// ---------------------------------------------------------------------------
// Kernel 0: no-op probe (keeps ncu -s 5 -c 1 landing on the MLP kernel)
// ---------------------------------------------------------------------------
__global__ void probe_kernel(int x) { (void)x; }

// ---------------------------------------------------------------------------
// Kernel 1: zero the message buffer
// ---------------------------------------------------------------------------
__global__ void zero_msgs_kernel(int n4) {
    int i = blockIdx.x * blockDim.x + threadIdx.x;
    if (i < n4) reinterpret_cast<float4*>(g_msgs)[i] = make_float4(0.f, 0.f, 0.f, 0.f);
}

// ---------------------------------------------------------------------------
// Kernel 2: scatter-add  messages[dst] += emb[src]   (edge_index int32)
// ---------------------------------------------------------------------------
__global__ void scatter_kernel(const int* __restrict__ ei,
                               const float* __restrict__ emb, int E) {
    long long idx = (long long)blockIdx.x * blockDim.x + threadIdx.x;
    if (idx >= (long long)E * 16) return;
    int e  = (int)(idx >> 4);
    int d4 = (int)(idx & 15);
    int src = ei[e];
    int dst = ei[E + e];
    float4 v = reinterpret_cast<const float4*>(emb + (size_t)src * EMBED)[d4];
    float* o = g_msgs + (size_t)dst * EMBED + d4 * 4;
    asm volatile("red.global.add.v4.f32 [%0], {%1, %2, %3, %4};"
                 :: "l"(o), "f"(v.x), "f"(v.y), "f"(v.z), "f"(v.w)
                 : "memory");
}

// ---------------------------------------------------------------------------
// Kernel 3: fused 2-layer MLP + residual, mma.sync bf16 3-product split.
// BARRIER-FREE mainloop: warps independently grab 16-node chunks; x A-frags
// built straight from gmem (coalesced LDG.64 quads), hidden layer stays in
// registers (D->A identity), only the tile-invariant WEIGHTS live in smem.
// 256 threads, 2 CTAs/SM.
// ---------------------------------------------------------------------------
__global__ void __launch_bounds__(NTH, 2) mlp_mma_kernel(
    const float* __restrict__ emb,
    const float* __restrict__ w1, const float* __restrict__ b1,
    const float* __restrict__ w2, const float* __restrict__ b2,
    float* __restrict__ out, int N)
{
    extern __shared__ char smem[];
    const uint32_t sb = smem_u32(smem);
    float* b1s = (float*)(smem + OFF_B1);
    float* b2s = (float*)(smem + OFF_B2);

    const int tid  = threadIdx.x;
    const int lane = tid & 31;
    const int wrp  = tid >> 5;          // 0..7

    // ---- stage weights hi/lo ONCE ----
    for (int i = tid; i < HID * EMBED; i += NTH) {      // w1[h][d]
        float v = w1[i];
        int h = i >> 6, d = i & 63;
        __nv_bfloat16 hb = __float2bfloat16(v);
        __nv_bfloat16 lb = __float2bfloat16(v - __bfloat162float(hb));
        *(uint16_t*)(smem + OFF_W1HI + (h * STRX + d) * 2) = __bfloat16_as_ushort(hb);
        *(uint16_t*)(smem + OFF_W1LO + (h * STRX + d) * 2) = __bfloat16_as_ushort(lb);
    }
    for (int i = tid; i < EMBED * HID; i += NTH) {      // w2[n][k]
        float v = w2[i];
        int n = i >> 7, k = i & 127;
        __nv_bfloat16 hb = __float2bfloat16(v);
        __nv_bfloat16 lb = __float2bfloat16(v - __bfloat162float(hb));
        *(uint16_t*)(smem + OFF_W2HI + (n * STRH + k) * 2) = __bfloat16_as_ushort(hb);
        *(uint16_t*)(smem + OFF_W2LO + (n * STRH + k) * 2) = __bfloat16_as_ushort(lb);
    }
    if (tid < HID)   b1s[tid] = b1[tid];
    if (tid < EMBED) b2s[tid] = b2[tid];
    __syncthreads();   // the ONLY barrier in the kernel

    const int dc = 2 * (lane & 3);     // fragment col pair base
    const int g  = lane >> 2;          // fragment row within 8

    const uint32_t b1_lane = (uint32_t)(lane & 15) * (STRX * 2)
                             + (uint32_t)(lane >> 4) * 16;
    const uint32_t b2_lane = (uint32_t)(lane & 15) * (STRH * 2)
                             + (uint32_t)(lane >> 4) * 16;

    const int nch    = (N + 15) >> 4;              // 16-node chunks
    const int gw     = blockIdx.x * (NTH / 32) + wrp;
    const int stride = gridDim.x * (NTH / 32);

    for (int ch = gw; ch < nch; ch += stride) {
        const int rg  = ch * 16 + g;
        const int rg8 = rg + 8;
        const bool va = rg < N, vb = rg8 < N;
        const float* p0 = g_msgs + (size_t)rg  * EMBED;
        const float* p1 = g_msgs + (size_t)rg8 * EMBED;

        // ---- A fragments straight from gmem (f32 -> bf16 hi/lo) ----
        // reg order per ks: [(g,2c), (g+8,2c), (g,2c+8), (g+8,2c+8)]
        uint32_t ahi[4][4], alo[4][4];
        const float2 z2 = make_float2(0.f, 0.f);
        #pragma unroll
        for (int ks = 0; ks < 4; ks++) {
            float2 v00 = va ? *(const float2*)(p0 + 16 * ks + dc)     : z2;
            float2 v10 = vb ? *(const float2*)(p1 + 16 * ks + dc)     : z2;
            float2 v01 = va ? *(const float2*)(p0 + 16 * ks + dc + 8) : z2;
            float2 v11 = vb ? *(const float2*)(p1 + 16 * ks + dc + 8) : z2;
            split_frag(v00, ahi[ks][0], alo[ks][0]);
            split_frag(v10, ahi[ks][1], alo[ks][1]);
            split_frag(v01, ahi[ks][2], alo[ks][2]);
            split_frag(v11, ahi[ks][3], alo[ks][3]);
        }

        // ---------------- GEMM1: 16 m x 128 h ----------------
        float acc[16][4];
        #pragma unroll
        for (int nt = 0; nt < 16; nt++) {
            float bb0 = b1s[nt * 8 + dc], bb1 = b1s[nt * 8 + dc + 1];
            acc[nt][0] = bb0; acc[nt][1] = bb1; acc[nt][2] = bb0; acc[nt][3] = bb1;
        }
        #pragma unroll
        for (int ks = 0; ks < 4; ks++) {
            #pragma unroll
            for (int pr = 0; pr < 8; pr++) {
                uint32_t bh[4], bl[4];
                uint32_t boff = (uint32_t)(pr * 16) * (STRX * 2) + b1_lane
                                + (uint32_t)ks * 32;
                ldm4(bh, sb + OFF_W1HI + boff);
                ldm4(bl, sb + OFF_W1LO + boff);
                mma16816(acc[2*pr],   ahi[ks], bh[0], bh[2]);
                mma16816(acc[2*pr],   ahi[ks], bl[0], bl[2]);
                mma16816(acc[2*pr],   alo[ks], bh[0], bh[2]);
                mma16816(acc[2*pr+1], ahi[ks], bh[1], bh[3]);
                mma16816(acc[2*pr+1], ahi[ks], bl[1], bl[3]);
                mma16816(acc[2*pr+1], alo[ks], bh[1], bh[3]);
            }
        }

        // ---- hidden in registers: relu + bf16 hi/lo -> GEMM2 A-frags ----
        uint32_t ah[8][4], al[8][4];
        #pragma unroll
        for (int ks = 0; ks < 8; ks++) {
            #pragma unroll
            for (int t = 0; t < 2; t++) {
                const float* a = acc[2 * ks + t];
                float f0 = fmaxf(a[0], 0.f), f1 = fmaxf(a[1], 0.f);
                float f2 = fmaxf(a[2], 0.f), f3 = fmaxf(a[3], 0.f);
                uint32_t ph01 = cvt2bf(f1, f0);
                uint32_t ph23 = cvt2bf(f3, f2);
                float h0 = __uint_as_float(ph01 << 16);
                float h1 = __uint_as_float(ph01 & 0xffff0000u);
                float h2 = __uint_as_float(ph23 << 16);
                float h3 = __uint_as_float(ph23 & 0xffff0000u);
                ah[ks][2 * t]     = ph01;
                ah[ks][2 * t + 1] = ph23;
                al[ks][2 * t]     = cvt2bf(f1 - h1, f0 - h0);
                al[ks][2 * t + 1] = cvt2bf(f3 - h3, f2 - h2);
            }
        }

        // ---------------- GEMM2: 16 m x 64 n (A from regs) ----------------
        float acc2[8][4];
        #pragma unroll
        for (int nt = 0; nt < 8; nt++) {
            float bb0 = b2s[nt * 8 + dc], bb1 = b2s[nt * 8 + dc + 1];
            acc2[nt][0] = bb0; acc2[nt][1] = bb1; acc2[nt][2] = bb0; acc2[nt][3] = bb1;
        }
        #pragma unroll
        for (int ks = 0; ks < 8; ks++) {
            #pragma unroll
            for (int pr = 0; pr < 4; pr++) {
                uint32_t bh[4], bl[4];
                uint32_t boff = (uint32_t)(pr * 16) * (STRH * 2) + b2_lane
                                + (uint32_t)ks * 32;
                ldm4(bh, sb + OFF_W2HI + boff);
                ldm4(bl, sb + OFF_W2LO + boff);
                mma16816(acc2[2*pr],   ah[ks], bh[0], bh[2]);
                mma16816(acc2[2*pr],   ah[ks], bl[0], bl[2]);
                mma16816(acc2[2*pr],   al[ks], bh[0], bh[2]);
                mma16816(acc2[2*pr+1], ah[ks], bh[1], bh[3]);
                mma16816(acc2[2*pr+1], ah[ks], bl[1], bl[3]);
                mma16816(acc2[2*pr+1], al[ks], bh[1], bh[3]);
            }
        }

        // ---- epilogue: relu + residual, float2 stores ----
        #pragma unroll
        for (int nt = 0; nt < 8; nt++) {
            int n = nt * 8 + dc;
            if (va) {
                float2 e = *(const float2*)(emb + (size_t)rg * EMBED + n);
                float2 o;
                o.x = e.x + fmaxf(acc2[nt][0], 0.f);
                o.y = e.y + fmaxf(acc2[nt][1], 0.f);
                *(float2*)(out + (size_t)rg * EMBED + n) = o;
            }
            if (vb) {
                float2 e = *(const float2*)(emb + (size_t)rg8 * EMBED + n);
                float2 o;
                o.x = e.x + fmaxf(acc2[nt][2], 0.f);
                o.y = e.y + fmaxf(acc2[nt][3], 0.f);
                *(float2*)(out + (size_t)rg8 * EMBED + n) = o;
            }
        }
    }
}

// ---------------------------------------------------------------------------
// Launch
// ---------------------------------------------------------------------------
extern "C" void kernel_launch(void* const* d_in, const int* in_sizes, int n_in,
                              void* d_out, int out_size) {
    const int*   ei  = (const int*)d_in[0];   // edge_index [2, E] int32
    const float* emb = (const float*)d_in[1]; // [N, 64]
    const float* w1  = (const float*)d_in[2]; // [128, 64]
    const float* b1  = (const float*)d_in[3]; // [128]
    const float* w2  = (const float*)d_in[4]; // [64, 128]
    const float* b2  = (const float*)d_in[5]; // [64]
    float*       out = (float*)d_out;

    int E = in_sizes[0] / 2;
    int N = in_sizes[1] / EMBED;

    static int nsm = 0;
    if (nsm == 0) {
        cudaDeviceGetAttribute(&nsm, cudaDevAttrMultiProcessorCount, 0);
        if (nsm <= 0) nsm = 148;
    }

    // 0) capture-alignment probe (no-op)
    probe_kernel<<<1, 32>>>(0);

    // 1) zero messages
    int n4 = N * (EMBED / 4);
    zero_msgs_kernel<<<(n4 + 255) / 256, 256>>>(n4);

    // 2) scatter-add
    long long total = (long long)E * 16;
    scatter_kernel<<<(unsigned)((total + 255) / 256), 256>>>(ei, emb, E);

    // 3) tensor-core fused MLP + residual (barrier-free, gmem A-frags,
    //    hidden in registers, 2 CTAs/SM)
    cudaFuncSetAttribute(mlp_mma_kernel, cudaFuncAttributeMaxDynamicSharedMemorySize,
                         SMEM_TOT);
    mlp_mma_kernel<<<nsm * 2, NTH, SMEM_TOT>>>(emb, w1, b1, w2, b2, out, N);
}

// round 15
// speedup vs baseline: 1.7212x; 1.1953x over previous
#include <cuda_runtime.h>
#include <cuda_fp16.h>
#include <cstdint>

#define EMBED 64
#define HID   128
#define MAXN  1000000
#define NTH   256

// Scratch: messages[N, 64]. __device__ global (no allocation allowed).
__device__ float g_msgs[(size_t)MAXN * EMBED];

// ---------------------------------------------------------------------------
// smem layout (bytes): hi-precision WEIGHTS ONLY (~36 KB).
// w1 rows: 72 u16 (144 B); w2 rows: 136 u16 (272 B) -> ldmatrix conflict-free.
// ---------------------------------------------------------------------------
#define STRX 72
#define STRH 136
#define OFF_W1HI 0
#define OFF_W2HI (OFF_W1HI + 128*STRX*2)
#define OFF_B1   (OFF_W2HI + 64*STRH*2)
#define OFF_B2   (OFF_B1 + 128*4)
#define SMEM_TOT (OFF_B2 + 64*4)           /* 36,608 B */

// ---------------------------------------------------------------------------
// PTX helpers
// ---------------------------------------------------------------------------
__device__ __forceinline__ uint32_t smem_u32(const void* p) {
    uint32_t a;
    asm("{ .reg .u64 t; cvta.to.shared.u64 t, %1; cvt.u32.u64 %0, t; }"
        : "=r"(a) : "l"(p));
    return a;
}
__device__ __forceinline__ void ldm4(uint32_t r[4], uint32_t addr) {
    asm volatile("ldmatrix.sync.aligned.m8n8.x4.shared.b16 {%0,%1,%2,%3}, [%4];"
                 : "=r"(r[0]), "=r"(r[1]), "=r"(r[2]), "=r"(r[3]) : "r"(addr));
}
__device__ __forceinline__ void mma16816(float c[4], const uint32_t a[4],
                                         uint32_t b0, uint32_t b1) {
    asm volatile(
        "mma.sync.aligned.m16n8k16.row.col.f32.f16.f16.f32 "
        "{%0,%1,%2,%3}, {%4,%5,%6,%7}, {%8,%9}, {%0,%1,%2,%3};"
        : "+f"(c[0]), "+f"(c[1]), "+f"(c[2]), "+f"(c[3])
        : "r"(a[0]), "r"(a[1]), "r"(a[2]), "r"(a[3]), "r"(b0), "r"(b1));
}
__device__ __forceinline__ uint32_t packh2(__half lo16, __half hi16) {
    __half2 h = __halves2half2(lo16, hi16);   // lo16 -> bits[15:0]
    return *reinterpret_cast<uint32_t*>(&h);
}
// split a float2 (v.x = lower col, v.y = upper col) into hi-frag + lo-frag regs
__device__ __forceinline__ void split_frag(float2 v, uint32_t& hi, uint32_t& lo) {
    __half hx = __float2half_rn(v.x), hy = __float2half_rn(v.y);
    __half lx = __float2half_rn(v.x - __half2float(hx));
    __half ly = __float2half_rn(v.y - __half2float(hy));
    hi = packh2(hx, hy);
    lo = packh2(lx, ly);
}

// ---------------------------------------------------------------------------
// Kernel 0: no-op probe (keeps ncu -s 5 -c 1 landing on the MLP kernel)
// ---------------------------------------------------------------------------
__global__ void probe_kernel(int x) { (void)x; }

// ---------------------------------------------------------------------------
// Kernel 1: zero the message buffer
// ---------------------------------------------------------------------------
__global__ void zero_msgs_kernel(int n4) {
    int i = blockIdx.x * blockDim.x + threadIdx.x;
    if (i < n4) reinterpret_cast<float4*>(g_msgs)[i] = make_float4(0.f, 0.f, 0.f, 0.f);
}

// ---------------------------------------------------------------------------
// Kernel 2: scatter-add  messages[dst] += emb[src]   (edge_index int32)
// ---------------------------------------------------------------------------
__global__ void scatter_kernel(const int* __restrict__ ei,
                               const float* __restrict__ emb, int E) {
    long long idx = (long long)blockIdx.x * blockDim.x + threadIdx.x;
    if (idx >= (long long)E * 16) return;
    int e  = (int)(idx >> 4);
    int d4 = (int)(idx & 15);
    int src = ei[e];
    int dst = ei[E + e];
    float4 v = reinterpret_cast<const float4*>(emb + (size_t)src * EMBED)[d4];
    float* o = g_msgs + (size_t)dst * EMBED + d4 * 4;
    asm volatile("red.global.add.v4.f32 [%0], {%1, %2, %3, %4};"
                 :: "l"(o), "f"(v.x), "f"(v.y), "f"(v.z), "f"(v.w)
                 : "memory");
}

// ---------------------------------------------------------------------------
// Kernel 3: fused 2-layer MLP + residual, mma.sync fp16 2-product split:
//   a*b ~= a_hi*b_hi + a_lo*b_hi   (b_lo pipeline deleted: LDSM traffic
//   halved, MMAs cut to 2/3 -- targets the L1=74% smem-bandwidth bound)
// BARRIER-FREE mainloop: warps independently grab 16-node chunks; A-frags
// built straight from gmem (coalesced LDG.64 quads), hidden layer stays in
// registers (D->A identity). 256 threads, 2 CTAs/SM.
// ---------------------------------------------------------------------------
__global__ void __launch_bounds__(NTH, 2) mlp_mma_kernel(
    const float* __restrict__ emb,
    const float* __restrict__ w1, const float* __restrict__ b1,
    const float* __restrict__ w2, const float* __restrict__ b2,
    float* __restrict__ out, int N)
{
    extern __shared__ char smem[];
    const uint32_t sb = smem_u32(smem);
    float* b1s = (float*)(smem + OFF_B1);
    float* b2s = (float*)(smem + OFF_B2);

    const int tid  = threadIdx.x;
    const int lane = tid & 31;
    const int wrp  = tid >> 5;          // 0..7

    // ---- stage weights (fp16 hi only) ONCE ----
    for (int i = tid; i < HID * EMBED; i += NTH) {      // w1[h][d]
        int h = i >> 6, d = i & 63;
        *(__half*)(smem + OFF_W1HI + (h * STRX + d) * 2) = __float2half_rn(w1[i]);
    }
    for (int i = tid; i < EMBED * HID; i += NTH) {      // w2[n][k]
        int n = i >> 7, k = i & 127;
        *(__half*)(smem + OFF_W2HI + (n * STRH + k) * 2) = __float2half_rn(w2[i]);
    }
    if (tid < HID)   b1s[tid] = b1[tid];
    if (tid < EMBED) b2s[tid] = b2[tid];
    __syncthreads();   // the ONLY barrier in the kernel

    const int dc = 2 * (lane & 3);     // fragment col pair base
    const int g  = lane >> 2;          // fragment row within 8

    const uint32_t b1_lane = (uint32_t)(lane & 15) * (STRX * 2)
                             + (uint32_t)(lane >> 4) * 16;
    const uint32_t b2_lane = (uint32_t)(lane & 15) * (STRH * 2)
                             + (uint32_t)(lane >> 4) * 16;

    const int nch    = (N + 15) >> 4;              // 16-node chunks
    const int gw     = blockIdx.x * (NTH / 32) + wrp;
    const int stride = gridDim.x * (NTH / 32);

    for (int ch = gw; ch < nch; ch += stride) {
        const int rg  = ch * 16 + g;
        const int rg8 = rg + 8;
        const bool va = rg < N, vb = rg8 < N;
        const float* p0 = g_msgs + (size_t)rg  * EMBED;
        const float* p1 = g_msgs + (size_t)rg8 * EMBED;

        // ---- A fragments straight from gmem (f32 -> fp16 hi/lo) ----
        // reg order per ks: [(g,2c), (g+8,2c), (g,2c+8), (g+8,2c+8)]
        uint32_t ahi[4][4], alo[4][4];
        const float2 z2 = make_float2(0.f, 0.f);
        #pragma unroll
        for (int ks = 0; ks < 4; ks++) {
            float2 v00 = va ? *(const float2*)(p0 + 16 * ks + dc)     : z2;
            float2 v10 = vb ? *(const float2*)(p1 + 16 * ks + dc)     : z2;
            float2 v01 = va ? *(const float2*)(p0 + 16 * ks + dc + 8) : z2;
            float2 v11 = vb ? *(const float2*)(p1 + 16 * ks + dc + 8) : z2;
            split_frag(v00, ahi[ks][0], alo[ks][0]);
            split_frag(v10, ahi[ks][1], alo[ks][1]);
            split_frag(v01, ahi[ks][2], alo[ks][2]);
            split_frag(v11, ahi[ks][3], alo[ks][3]);
        }

        // ---------------- GEMM1: 16 m x 128 h ----------------
        float acc[16][4];
        #pragma unroll
        for (int nt = 0; nt < 16; nt++) {
            float bb0 = b1s[nt * 8 + dc], bb1 = b1s[nt * 8 + dc + 1];
            acc[nt][0] = bb0; acc[nt][1] = bb1; acc[nt][2] = bb0; acc[nt][3] = bb1;
        }
        #pragma unroll
        for (int ks = 0; ks < 4; ks++) {
            #pragma unroll
            for (int pr = 0; pr < 8; pr++) {
                uint32_t bh[4];
                uint32_t boff = (uint32_t)(pr * 16) * (STRX * 2) + b1_lane
                                + (uint32_t)ks * 32;
                ldm4(bh, sb + OFF_W1HI + boff);
                mma16816(acc[2*pr],   ahi[ks], bh[0], bh[2]);
                mma16816(acc[2*pr],   alo[ks], bh[0], bh[2]);
                mma16816(acc[2*pr+1], ahi[ks], bh[1], bh[3]);
                mma16816(acc[2*pr+1], alo[ks], bh[1], bh[3]);
            }
        }

        // ---- hidden in registers: relu + fp16 hi/lo -> GEMM2 A-frags ----
        uint32_t ah[8][4], al[8][4];
        #pragma unroll
        for (int ks = 0; ks < 8; ks++) {
            #pragma unroll
            for (int t = 0; t < 2; t++) {
                const float* a = acc[2 * ks + t];
                float2 f01 = make_float2(fmaxf(a[0], 0.f), fmaxf(a[1], 0.f));
                float2 f23 = make_float2(fmaxf(a[2], 0.f), fmaxf(a[3], 0.f));
                split_frag(f01, ah[ks][2 * t],     al[ks][2 * t]);
                split_frag(f23, ah[ks][2 * t + 1], al[ks][2 * t + 1]);
            }
        }

        // ---------------- GEMM2: 16 m x 64 n (A from regs) ----------------
        float acc2[8][4];
        #pragma unroll
        for (int nt = 0; nt < 8; nt++) {
            float bb0 = b2s[nt * 8 + dc], bb1 = b2s[nt * 8 + dc + 1];
            acc2[nt][0] = bb0; acc2[nt][1] = bb1; acc2[nt][2] = bb0; acc2[nt][3] = bb1;
        }
        #pragma unroll
        for (int ks = 0; ks < 8; ks++) {
            #pragma unroll
            for (int pr = 0; pr < 4; pr++) {
                uint32_t bh[4];
                uint32_t boff = (uint32_t)(pr * 16) * (STRH * 2) + b2_lane
                                + (uint32_t)ks * 32;
                ldm4(bh, sb + OFF_W2HI + boff);
                mma16816(acc2[2*pr],   ah[ks], bh[0], bh[2]);
                mma16816(acc2[2*pr],   al[ks], bh[0], bh[2]);
                mma16816(acc2[2*pr+1], ah[ks], bh[1], bh[3]);
                mma16816(acc2[2*pr+1], al[ks], bh[1], bh[3]);
            }
        }

        // ---- epilogue: relu + residual, float2 stores ----
        #pragma unroll
        for (int nt = 0; nt < 8; nt++) {
            int n = nt * 8 + dc;
            if (va) {
                float2 e = *(const float2*)(emb + (size_t)rg * EMBED + n);
                float2 o;
                o.x = e.x + fmaxf(acc2[nt][0], 0.f);
                o.y = e.y + fmaxf(acc2[nt][1], 0.f);
                *(float2*)(out + (size_t)rg * EMBED + n) = o;
            }
            if (vb) {
                float2 e = *(const float2*)(emb + (size_t)rg8 * EMBED + n);
                float2 o;
                o.x = e.x + fmaxf(acc2[nt][2], 0.f);
                o.y = e.y + fmaxf(acc2[nt][3], 0.f);
                *(float2*)(out + (size_t)rg8 * EMBED + n) = o;
            }
        }
    }
}

// ---------------------------------------------------------------------------
// Launch
// ---------------------------------------------------------------------------
extern "C" void kernel_launch(void* const* d_in, const int* in_sizes, int n_in,
                              void* d_out, int out_size) {
    const int*   ei  = (const int*)d_in[0];   // edge_index [2, E] int32
    const float* emb = (const float*)d_in[1]; // [N, 64]
    const float* w1  = (const float*)d_in[2]; // [128, 64]
    const float* b1  = (const float*)d_in[3]; // [128]
    const float* w2  = (const float*)d_in[4]; // [64, 128]
    const float* b2  = (const float*)d_in[5]; // [64]
    float*       out = (float*)d_out;

    int E = in_sizes[0] / 2;
    int N = in_sizes[1] / EMBED;

    static int nsm = 0;
    if (nsm == 0) {
        cudaDeviceGetAttribute(&nsm, cudaDevAttrMultiProcessorCount, 0);
        if (nsm <= 0) nsm = 148;
    }

    // 0) capture-alignment probe (no-op)
    probe_kernel<<<1, 32>>>(0);

    // 1) zero messages
    int n4 = N * (EMBED / 4);
    zero_msgs_kernel<<<(n4 + 255) / 256, 256>>>(n4);

    // 2) scatter-add
    long long total = (long long)E * 16;
    scatter_kernel<<<(unsigned)((total + 255) / 256), 256>>>(ei, emb, E);

    // 3) tensor-core fused MLP + residual (fp16 2-product, barrier-free,
    //    gmem A-frags, hidden in registers, 2 CTAs/SM)
    cudaFuncSetAttribute(mlp_mma_kernel, cudaFuncAttributeMaxDynamicSharedMemorySize,
                         SMEM_TOT);
    mlp_mma_kernel<<<nsm * 2, NTH, SMEM_TOT>>>(emb, w1, b1, w2, b2, out, N);
}